// round 1
// baseline (speedup 1.0000x reference)
#include <cuda_runtime.h>
#include <cuda_bf16.h>
#include <cstdint>

// ---------------------------------------------------------------------------
// Model_1580547965011:
//   embedded = (emb[text] @ fc0_w.T + fc0_b) * valid_mask         (1024,50,32)
//   scores   = tanh(embedded @ (wq+wk).T) @ att_v  (masked)       (1024,50)
//   attn     = softmax(scores)                                    (1024,50)
//   sg = attn-weighted sum of embedded ; sl = embedded[:, -1]
//   hidden   = concat(sg,sl) @ out_w.T + out_b                    (1024,32)
//   out      = hidden @ (emb @ fc0_w.T + fc0_b).T                 (1024,128000)
//
// Key algebraic reduction for the big GEMM:
//   out[b,v] = h2[b] . emb[v] + c[b]
//   where h2[b] = hidden[b] @ fc0_w   (16)   and c[b] = hidden[b] . fc0_b
// => rank-16 instead of rank-32, and item_vecs never materialized.
// ---------------------------------------------------------------------------

#define VOCAB 128000
#define EMB   32
#define HALF  16
#define BATCH 1024
#define SEQ   50

__device__ __align__(16) float g_h2[BATCH * HALF];
__device__ __align__(16) float g_c[BATCH];

// ---------------- f32x2 packed math (Blackwell; PTX-only) -------------------
__device__ __forceinline__ unsigned long long pk2(float lo, float hi) {
    unsigned long long r;
    asm("mov.b64 %0, {%1, %2};" : "=l"(r) : "f"(lo), "f"(hi));
    return r;
}
__device__ __forceinline__ void unpk2(unsigned long long v, float& lo, float& hi) {
    asm("mov.b64 {%0, %1}, %2;" : "=f"(lo), "=f"(hi) : "l"(v));
}
__device__ __forceinline__ unsigned long long mul2(unsigned long long a, unsigned long long b) {
    unsigned long long d;
    asm("mul.rn.f32x2 %0, %1, %2;" : "=l"(d) : "l"(a), "l"(b));
    return d;
}
__device__ __forceinline__ unsigned long long fma2(unsigned long long a, unsigned long long b,
                                                   unsigned long long c) {
    unsigned long long d;
    asm("fma.rn.f32x2 %0, %1, %2, %3;" : "=l"(d) : "l"(a), "l"(b), "l"(c));
    return d;
}

// ---------------------------------------------------------------------------
// Kernel 1: one warp per batch row. Produces g_h2[b][0:16], g_c[b].
// ---------------------------------------------------------------------------
__global__ void __launch_bounds__(32) k1_attend(
    const int*   __restrict__ text,
    const float* __restrict__ emb,
    const float* __restrict__ fc0_w,
    const float* __restrict__ fc0_b,
    const float* __restrict__ wq,
    const float* __restrict__ wk,
    const float* __restrict__ av,
    const float* __restrict__ out_w,
    const float* __restrict__ out_b)
{
    const int b = blockIdx.x;
    const int e = threadIdx.x;  // 0..31

    __shared__ float s_emb[SEQ][EMB];
    __shared__ float s_attn[SEQ];
    __shared__ float s_vec[3][EMB];   // sg, sl, hidden
    __shared__ int   s_tok[SEQ];

    if (e < 25) {
        s_tok[e]      = text[b * SEQ + e];
        s_tok[e + 25] = text[b * SEQ + e + 25];
    }

    float w0[HALF];
#pragma unroll
    for (int h = 0; h < HALF; h++) w0[h] = fc0_w[e * HALF + h];
    const float vb  = fc0_b[e];
    const float ave = av[e];
    float W[EMB];
#pragma unroll
    for (int j = 0; j < EMB; j++) W[j] = wq[e * EMB + j] + wk[e * EMB + j];
    __syncthreads();

    // embedded[s][e]
#pragma unroll 2
    for (int s = 0; s < SEQ; s++) {
        const int tok = s_tok[s];
        const float4* er = reinterpret_cast<const float4*>(emb + (size_t)tok * HALF);
        float4 q0 = __ldg(er + 0), q1 = __ldg(er + 1), q2 = __ldg(er + 2), q3 = __ldg(er + 3);
        float acc = vb;
        acc += q0.x * w0[0]  + q0.y * w0[1]  + q0.z * w0[2]  + q0.w * w0[3];
        acc += q1.x * w0[4]  + q1.y * w0[5]  + q1.z * w0[6]  + q1.w * w0[7];
        acc += q2.x * w0[8]  + q2.y * w0[9]  + q2.z * w0[10] + q2.w * w0[11];
        acc += q3.x * w0[12] + q3.y * w0[13] + q3.z * w0[14] + q3.w * w0[15];
        const bool valid = (tok != 0) && (tok != 1);
        s_emb[s][e] = valid ? acc : 0.0f;
    }
    __syncthreads();

    // scores[s] = tanh(embedded[s] @ W.T) . av   (lane e handles component e)
    for (int s = 0; s < SEQ; s++) {
        float t = 0.0f;
#pragma unroll
        for (int j = 0; j < EMB; j++) t += s_emb[s][j] * W[j];
        float sc = tanhf(t) * ave;
#pragma unroll
        for (int o = 16; o > 0; o >>= 1) sc += __shfl_xor_sync(0xffffffffu, sc, o);
        if (e == 0) {
            const int tok = s_tok[s];
            const bool valid = (tok != 0) && (tok != 1);
            s_attn[s] = valid ? sc : -1000000000.0f;
        }
    }
    __syncthreads();

    // softmax over SEQ=50: lane e covers s=e and (e<18) s=e+32
    {
        float sc0 = s_attn[e];
        float sc1 = (e < SEQ - 32) ? s_attn[e + 32] : -3.4e38f;
        float m = fmaxf(sc0, sc1);
#pragma unroll
        for (int o = 16; o > 0; o >>= 1) m = fmaxf(m, __shfl_xor_sync(0xffffffffu, m, o));
        float ex0 = __expf(sc0 - m);
        float ex1 = (e < SEQ - 32) ? __expf(sc1 - m) : 0.0f;
        float ssum = ex0 + ex1;
#pragma unroll
        for (int o = 16; o > 0; o >>= 1) ssum += __shfl_xor_sync(0xffffffffu, ssum, o);
        const float inv = 1.0f / ssum;
        s_attn[e] = ex0 * inv;
        if (e < SEQ - 32) s_attn[e + 32] = ex1 * inv;
    }
    __syncthreads();

    // sg[e], sl[e]
    float sg = 0.0f;
#pragma unroll 2
    for (int s = 0; s < SEQ; s++) sg += s_attn[s] * s_emb[s][e];
    s_vec[0][e] = sg;
    s_vec[1][e] = s_emb[SEQ - 1][e];
    __syncthreads();

    // hidden[e]
    float hid = out_b[e];
    const float* owr = out_w + e * 2 * EMB;
#pragma unroll
    for (int j = 0; j < EMB; j++)
        hid += s_vec[0][j] * owr[j] + s_vec[1][j] * owr[EMB + j];
    s_vec[2][e] = hid;
    __syncthreads();

    // h2[b][h] = sum_e hidden[e] * fc0_w[e][h];  c[b] = hidden . fc0_b
    if (e < HALF) {
        float a = 0.0f;
#pragma unroll
        for (int j = 0; j < EMB; j++) a += s_vec[2][j] * fc0_w[j * HALF + e];
        g_h2[b * HALF + e] = a;
    }
    float cp = hid * vb;
#pragma unroll
    for (int o = 16; o > 0; o >>= 1) cp += __shfl_xor_sync(0xffffffffu, cp, o);
    if (e == 0) g_c[b] = cp;
}

// ---------------------------------------------------------------------------
// Kernel 2: out[b,v] = h2[b] . emb[v] + c[b]   (rank-16, f32x2 packed)
// grid (125, 8), 256 threads. Thread owns 4 consecutive v rows in registers;
// loops over 128 b rows (h2 tile in smem). STG.128 streaming stores.
// ---------------------------------------------------------------------------
#define K2_THREADS 256
#define K2_TV      4
#define K2_BT      128

__global__ void __launch_bounds__(K2_THREADS) k2_score(
    const float* __restrict__ emb,
    float*       __restrict__ out)
{
    __shared__ float4 sh2[K2_BT * (HALF / 4)];  // 512 float4
    __shared__ float  shc[K2_BT];

    const int tid = threadIdx.x;
    const int b0  = blockIdx.y * K2_BT;

    const float4* h2g = reinterpret_cast<const float4*>(g_h2 + (size_t)b0 * HALF);
    sh2[tid]       = h2g[tid];
    sh2[tid + 256] = h2g[tid + 256];
    if (tid < K2_BT) shc[tid] = g_c[b0 + tid];
    __syncthreads();

    const size_t v0 = ((size_t)blockIdx.x * K2_THREADS + tid) * K2_TV;

    // emb rows v0..v0+3 packed as f32x2 along h
    unsigned long long e2[K2_TV][HALF / 2];
#pragma unroll
    for (int v = 0; v < K2_TV; v++) {
        const float4* er = reinterpret_cast<const float4*>(emb + (v0 + v) * HALF);
#pragma unroll
        for (int q = 0; q < 4; q++) {
            float4 f = __ldg(er + q);
            e2[v][q * 2]     = pk2(f.x, f.y);
            e2[v][q * 2 + 1] = pk2(f.z, f.w);
        }
    }

    float4* obase = reinterpret_cast<float4*>(out + v0);
    const size_t row4 = (size_t)VOCAB / 4;  // float4 stride per b row

    for (int bb = 0; bb < K2_BT; bb++) {
        unsigned long long h[HALF / 2];
#pragma unroll
        for (int q = 0; q < 4; q++) {
            float4 f = sh2[bb * 4 + q];
            h[q * 2]     = pk2(f.x, f.y);
            h[q * 2 + 1] = pk2(f.z, f.w);
        }
        const float cb = shc[bb];

        float r[K2_TV];
#pragma unroll
        for (int v = 0; v < K2_TV; v++) {
            unsigned long long acc = mul2(e2[v][0], h[0]);
#pragma unroll
            for (int p = 1; p < HALF / 2; p++) acc = fma2(e2[v][p], h[p], acc);
            float lo, hi;
            unpk2(acc, lo, hi);
            r[v] = lo + hi + cb;
        }
        float4 res = make_float4(r[0], r[1], r[2], r[3]);
        __stcs(obase + (size_t)(b0 + bb) * row4, res);
    }
}

// ---------------------------------------------------------------------------
extern "C" void kernel_launch(void* const* d_in, const int* in_sizes, int n_in,
                              void* d_out, int out_size)
{
    const int*   text   = (const int*)  d_in[0];
    const float* emb    = (const float*)d_in[1];
    const float* fc0_w  = (const float*)d_in[2];
    const float* fc0_b  = (const float*)d_in[3];
    const float* att_wq = (const float*)d_in[4];
    const float* att_wk = (const float*)d_in[5];
    const float* att_v  = (const float*)d_in[6];
    const float* out_w  = (const float*)d_in[7];
    const float* out_b  = (const float*)d_in[8];
    float* out = (float*)d_out;

    k1_attend<<<BATCH, 32>>>(text, emb, fc0_w, fc0_b, att_wq, att_wk, att_v, out_w, out_b);

    dim3 grid(VOCAB / (K2_THREADS * K2_TV), BATCH / K2_BT);  // (125, 8)
    k2_score<<<grid, K2_THREADS>>>(emb, out);
}